// round 8
// baseline (speedup 1.0000x reference)
#include <cuda_runtime.h>

namespace {
constexpr int kB = 2, kNP = 4, kN = 64, kP = 24, kCin = 16, kC = 32, kT = 96;
constexpr int kRows = kB * kNP * kN * kP;                                // 12288
constexpr long long kAttElems = (long long)kB * kN * kN * kT * kC;       // 25165824
constexpr int kPad = 36;          // smem row stride (floats), 16B-aligned
constexpr float kLog2e = 1.4426950408889634f;
}

__device__ float g_h[kRows * kC];   // h = x @ W, (B*6144, 32) row-major

__device__ __forceinline__ float ex2f(float x) {
    float r; asm("ex2.approx.f32 %0, %1;" : "=f"(r) : "f"(x)); return r;
}
__device__ __forceinline__ float rcpf(float x) {
    float r; asm("rcp.approx.f32 %0, %1;" : "=f"(r) : "f"(x)); return r;
}

// Kernel 1: h = x @ W. One thread = one row x 4-channel quad.
__global__ void h_kernel(const float* __restrict__ x, const float* __restrict__ W) {
    int gid = blockIdx.x * 256 + threadIdx.x;   // 98304 threads
    int q = gid & 7;                            // channel quad (c = 4q..4q+3)
    int row = gid >> 3;
    const float4* xr = (const float4*)(x + row * kCin);
    const float4* Wq = (const float4*)W + q;    // quad of W row k is at k*8+q
    float4 a0 = __ldg(xr), a1 = __ldg(xr + 1), a2 = __ldg(xr + 2), a3 = __ldg(xr + 3);
    float4 acc = make_float4(0.f, 0.f, 0.f, 0.f);
#define FMA4(s, k) { float4 w = __ldg(Wq + (k) * 8); \
    acc.x = fmaf(s, w.x, acc.x); acc.y = fmaf(s, w.y, acc.y); \
    acc.z = fmaf(s, w.z, acc.z); acc.w = fmaf(s, w.w, acc.w); }
    FMA4(a0.x, 0)  FMA4(a0.y, 1)  FMA4(a0.z, 2)  FMA4(a0.w, 3)
    FMA4(a1.x, 4)  FMA4(a1.y, 5)  FMA4(a1.z, 6)  FMA4(a1.w, 7)
    FMA4(a2.x, 8)  FMA4(a2.y, 9)  FMA4(a2.z, 10) FMA4(a2.w, 11)
    FMA4(a3.x, 12) FMA4(a3.y, 13) FMA4(a3.z, 14) FMA4(a3.w, 15)
#undef FMA4
    *(float4*)(g_h + row * kC + q * 4) = acc;
}

// Kernel 2: warp = (b,s,i,p); 8-lane group owns one j (4 j's/iter, 16 iters);
// lane owns 4 channels. LeakyReLU*adj*log2e = A1*x + A2*|x| with
// A1=0.6*a, A2=0.4*a (a = adj*log2e >= 0). All loop addresses are
// immediate offsets from loop-invariant bases (fully unrolled).
__global__ void __launch_bounds__(256, 6)
att_kernel(const float* __restrict__ adj, float* __restrict__ out) {
    __shared__ float  hs[kN * kPad];   // 64 rows of h[b,s,j,p,:]
    __shared__ float2 as2[8 * kN];     // (0.6*a, 0.4*a) per (i,j)

    const int tid  = threadIdx.x;
    const int warp = tid >> 5;
    const int lane = tid & 31;
    const int lg   = lane & 7;         // channel group: c = 4*lg..4*lg+3
    const int grp  = lane >> 3;        // j subgroup within warp (0..3)

    const int p  = blockIdx.x % kP;
    const int bs = blockIdx.x / kP;
    const int s  = bs & 3;
    const int b  = bs >> 2;
    const int i0 = (int)blockIdx.y * 8;
    const int i  = i0 + warp;

    // Stage h rows (512 float4); row j lives at +j*768 floats in g_h
    const float4* hb = (const float4*)(g_h + (b * 6144 + s * 1536 + p) * 32);
#pragma unroll
    for (int r = 0; r < 2; ++r) {
        int idx = tid + r * 256;            // 0..511
        int jj = idx >> 3, q = idx & 7;
        *(float4*)(hs + jj * kPad + q * 4) = __ldg(hb + jj * 192 + q);
    }
    // Stage pre-scaled adjacency for this block's 8 i's
#pragma unroll
    for (int r = 0; r < 2; ++r) {
        int idx = tid + r * 256;
        float a = __ldg(adj + (i0 + (idx >> 6)) * kN + (idx & 63)) * kLog2e;
        as2[idx] = make_float2(0.6f * a, 0.4f * a);
    }
    __syncthreads();

    // h_i channels owned by this lane
    const float4 hiv = *(const float4*)(hs + i * kPad + lg * 4);

    const int t = p * kNP + s;
    // Loop-invariant bases (j = grp + 4*jg)
    float* dstb = out + (((long long)(b * kN + i) * kN + grp) * kT + t) * kC + lg * 4;
    const float*  hrb = hs + grp * kPad + lg * 4;
    const float2* awb = as2 + warp * kN + grp;

    float rs0 = 0.f, rs1 = 0.f, rs2 = 0.f, rs3 = 0.f;
#pragma unroll
    for (int jg = 0; jg < 16; ++jg) {
        const float4 hj = *(const float4*)(hrb + jg * (4 * kPad));
        const float2 A = awb[jg * 4];

        float x0 = hiv.x * hj.x, x1 = hiv.y * hj.y;
        float x2 = hiv.z * hj.z, x3 = hiv.w * hj.w;
        float e0 = ex2f(fmaf(A.x, x0, A.y * fabsf(x0)));
        float e1 = ex2f(fmaf(A.x, x1, A.y * fabsf(x1)));
        float e2 = ex2f(fmaf(A.x, x2, A.y * fabsf(x2)));
        float e3 = ex2f(fmaf(A.x, x3, A.y * fabsf(x3)));

        float sl = (e0 + e1) + (e2 + e3);
        sl += __shfl_xor_sync(0xffffffffu, sl, 1);
        sl += __shfl_xor_sync(0xffffffffu, sl, 2);
        sl += __shfl_xor_sync(0xffffffffu, sl, 4);
        const float inv = rcpf(sl);

        float o0 = e0 * inv, o1 = e1 * inv, o2 = e2 * inv, o3 = e3 * inv;
        rs0 += o0; rs1 += o1; rs2 += o2; rs3 += o3;
        *(float4*)(dstb + jg * (4 * kT * kC)) = make_float4(o0, o1, o2, o3);
    }

    // Reduce rsum across the 4 j-subgroups (lane bits 3,4)
    rs0 += __shfl_xor_sync(0xffffffffu, rs0, 8);
    rs1 += __shfl_xor_sync(0xffffffffu, rs1, 8);
    rs2 += __shfl_xor_sync(0xffffffffu, rs2, 8);
    rs3 += __shfl_xor_sync(0xffffffffu, rs3, 8);
    rs0 += __shfl_xor_sync(0xffffffffu, rs0, 16);
    rs1 += __shfl_xor_sync(0xffffffffu, rs1, 16);
    rs2 += __shfl_xor_sync(0xffffffffu, rs2, 16);
    rs3 += __shfl_xor_sync(0xffffffffu, rs3, 16);

    if (grp == 0) {   // lanes 0..7 hold full sums for channels 4*lg..4*lg+3
        const int sh = t / kP, ph = t % kP;     // h_flat decomposition of t
        const float4 hv = *(const float4*)(g_h +
            (b * 6144 + sh * 1536 + i * kP + ph) * 32 + lg * 4);
        float h0 = rs0 * hv.x, h1 = rs1 * hv.y, h2 = rs2 * hv.z, h3 = rs3 * hv.w;
        float4 r;
        r.x = h0 > 0.f ? h0 : expm1f(h0);
        r.y = h1 > 0.f ? h1 : expm1f(h1);
        r.z = h2 > 0.f ? h2 : expm1f(h2);
        r.w = h3 > 0.f ? h3 : expm1f(h3);
        *(float4*)(out + kAttElems +
                   ((long long)(b * kN + i) * kT + t) * kC + lg * 4) = r;
    }
}

extern "C" void kernel_launch(void* const* d_in, const int* in_sizes, int n_in,
                              void* d_out, int out_size) {
    const float* x   = (const float*)d_in[0];
    const float* adj = (const float*)d_in[1];
    const float* W   = (const float*)d_in[2];
    float* out = (float*)d_out;

    h_kernel<<<(kRows * kC / 4) / 256, 256>>>(x, W);   // 384 blocks

    dim3 grid(kB * kNP * kP, kN / 8);   // (192, 8)
    att_kernel<<<grid, 256>>>(adj, out);
}